// round 1
// baseline (speedup 1.0000x reference)
#include <cuda_runtime.h>
#include <cuda_bf16.h>

// Problem constants
#define B_     128
#define CIN    128     // INA
#define LEGO_  128
#define OUTC   512
#define HW     1024    // 32*32
#define W_IMG  32

// CSR map: LEGO channel -> list of output channels o with sel[o]==l
__device__ int   g_off[LEGO_ + 1];
__device__ int   g_list[OUTC];
__device__ float g_lscale[OUTC];

// ---------------------------------------------------------------------------
// Kernel 1: compute sel[o] = argmax_l comb[0,o,l], scale[o] = coeff[0,o,sel],
// and build the inverse CSR map. One block, 512 threads.
// ---------------------------------------------------------------------------
__global__ void select_kernel(const float* __restrict__ coeff,
                              const float* __restrict__ comb) {
    __shared__ int   s_cnt[LEGO_];
    __shared__ int   s_off[LEGO_ + 1];
    __shared__ int   s_cur[LEGO_];

    int o = threadIdx.x;             // 0..511
    if (o < LEGO_) s_cnt[o] = 0;
    __syncthreads();

    // argmax over l (first occurrence of max -> strict '>')
    const float* row = comb + o * LEGO_;   // split 0 slice
    float m  = row[0];
    int   mi = 0;
    #pragma unroll 4
    for (int l = 1; l < LEGO_; l++) {
        float v = row[l];
        if (v > m) { m = v; mi = l; }
    }
    float sc = coeff[o * LEGO_ + mi];
    atomicAdd(&s_cnt[mi], 1);
    __syncthreads();

    if (o == 0) {
        int acc = 0;
        for (int l = 0; l < LEGO_; l++) { s_off[l] = acc; acc += s_cnt[l]; }
        s_off[LEGO_] = acc;   // == 512
    }
    __syncthreads();

    if (o < LEGO_) { s_cur[o] = s_off[o]; g_off[o] = s_off[o]; }
    if (o == 0)    g_off[LEGO_] = s_off[LEGO_];
    __syncthreads();

    int pos = atomicAdd(&s_cur[mi], 1);
    g_list[pos]   = o;
    g_lscale[pos] = sc;
}

// ---------------------------------------------------------------------------
// Kernel 2: fused per-batch 3x3 conv (weights gathered by label) + scaled
// scatter to output channels.
// grid = (16 channel-groups, 128 batches), block = 256 threads.
// Each block: batch b, 8 LEGO channels. Each thread: 1x4 pixel strip.
// ---------------------------------------------------------------------------
#define XS_STRIDE 35   // 34 used + 1 pad: conflict-free LDS (3r+4c0 pattern)

__global__ __launch_bounds__(256, 2)
void conv_scatter_kernel(const float* __restrict__ x,
                         const int*   __restrict__ label,
                         const float* __restrict__ ff,
                         float*       __restrict__ out) {
    const int g = blockIdx.x;        // 0..15 : group of 8 LEGO channels
    const int b = blockIdx.y;        // 0..127
    const int t = threadIdx.x;       // 0..255

    __shared__ float xs[4][34 * XS_STRIDE];   // 4 in-ch, padded 34x34 image
    __shared__ float ws[8][4][9];             // 8 oc x 4 ic x 9 taps

    // zero the whole staging buffer once: halo stays zero across chunks
    for (int i = t; i < 4 * 34 * XS_STRIDE; i += 256)
        (&xs[0][0])[i] = 0.0f;

    const int lab = label[b];
    const int ocb = g * 8;
    const float* xb = x  + (size_t)b * CIN * HW;
    const float* wb = ff + ((size_t)lab * LEGO_ + ocb) * CIN * 9;

    float acc[8][4];
    #pragma unroll
    for (int oo = 0; oo < 8; oo++)
        #pragma unroll
        for (int p = 0; p < 4; p++) acc[oo][p] = 0.0f;

    const int r  = t >> 3;            // pixel row 0..31
    const int c0 = (t & 7) * 4;       // pixel col base 0..28

    for (int ic0 = 0; ic0 < CIN; ic0 += 4) {
        __syncthreads();              // previous compute done before overwrite

        // ---- stage 4 input channels (interior only; halo already zero) ----
        #pragma unroll
        for (int cc = 0; cc < 4; cc++) {
            float4 v4 = *reinterpret_cast<const float4*>(
                            xb + (ic0 + cc) * HW + t * 4);
            float* dst = &xs[cc][(r + 1) * XS_STRIDE + (c0 + 1)];
            dst[0] = v4.x; dst[1] = v4.y; dst[2] = v4.z; dst[3] = v4.w;
        }
        // ---- stage weights: 8 oc x 4 ic x 9 = 288 floats ----
        for (int e = t; e < 288; e += 256) {
            int oo  = e / 36;
            int rem = e % 36;
            int icc = rem / 9;
            int k   = rem % 9;
            ws[oo][icc][k] = wb[((size_t)oo * CIN + ic0 + icc) * 9 + k];
        }
        __syncthreads();

        // ---- compute ----
        #pragma unroll
        for (int cc = 0; cc < 4; cc++) {
            float v[3][6];
            #pragma unroll
            for (int kh = 0; kh < 3; kh++)
                #pragma unroll
                for (int j = 0; j < 6; j++)
                    v[kh][j] = xs[cc][(r + kh) * XS_STRIDE + c0 + j];

            #pragma unroll
            for (int oo = 0; oo < 8; oo++) {
                #pragma unroll
                for (int kh = 0; kh < 3; kh++) {
                    #pragma unroll
                    for (int kw = 0; kw < 3; kw++) {
                        float wv = ws[oo][cc][kh * 3 + kw];
                        acc[oo][0] = fmaf(wv, v[kh][kw + 0], acc[oo][0]);
                        acc[oo][1] = fmaf(wv, v[kh][kw + 1], acc[oo][1]);
                        acc[oo][2] = fmaf(wv, v[kh][kw + 2], acc[oo][2]);
                        acc[oo][3] = fmaf(wv, v[kh][kw + 3], acc[oo][3]);
                    }
                }
            }
        }
    }

    // ---- fused scatter epilogue: write every output channel mapped here ----
    const int pix = r * W_IMG + c0;
    #pragma unroll
    for (int oo = 0; oo < 8; oo++) {
        const int oc = ocb + oo;
        const int s  = g_off[oc];
        const int e  = g_off[oc + 1];
        for (int idx = s; idx < e; idx++) {
            const int   o  = g_list[idx];
            const float sc = g_lscale[idx];
            float4 w4 = make_float4(acc[oo][0] * sc, acc[oo][1] * sc,
                                    acc[oo][2] * sc, acc[oo][3] * sc);
            *reinterpret_cast<float4*>(
                out + ((size_t)b * OUTC + o) * HW + pix) = w4;
        }
    }
}

// ---------------------------------------------------------------------------
extern "C" void kernel_launch(void* const* d_in, const int* in_sizes, int n_in,
                              void* d_out, int out_size) {
    const float* x     = (const float*)d_in[0];
    const int*   label = (const int*)  d_in[1];
    const float* ff    = (const float*)d_in[2];
    const float* coeff = (const float*)d_in[3];   // second_filter_coefficients
    const float* comb  = (const float*)d_in[4];   // second_filter_combination
    float*       out   = (float*)d_out;

    select_kernel<<<1, OUTC>>>(coeff, comb);

    dim3 grid(16, B_);     // same-batch blocks adjacent -> L2 reuse of x[b]
    conv_scatter_kernel<<<grid, 256>>>(x, label, ff, out);
}